// round 14
// baseline (speedup 1.0000x reference)
#include <cuda_runtime.h>

#define NB    32
#define TLEN  4096
#define NF    128
#define NFFT  4096
#define KTOP  16
#define WIN   25
#define HALF  12
#define THR   256
#define BUFSZ 4352
#define PAD(i) ((i) + ((i) >> 4))

typedef unsigned long long u64;

__device__ float2 g_twf[NFFT];                    // e^{-2pi i k / 4096}
__device__ float2 g_H[NFFT/2 + 1];                // Hamming freq response * (1/4096)

__device__ __forceinline__ float2 cmul(float2 a, float2 b) {
    return make_float2(fmaf(a.x, b.x, -a.y * b.y), fmaf(a.x, b.y, a.y * b.x));
}

// ---------------------------------------------------------------- init
__global__ void init_kernel() {
    int k = blockIdx.x * blockDim.x + threadIdx.x;
    if (k < NFFT) {
        double a = -(double)k / 2048.0;
        g_twf[k] = make_float2((float)cospi(a), (float)sinpi(a));
    }
    if (k <= NFFT/2) {
        float hr = 0.f, hi = 0.f;
        #pragma unroll 1
        for (int n = 0; n < WIN; n++) {
            float w = (0.54f - 0.46f * cospif(2.0f * (float)n / 25.0f)) * (1.0f / 13.5f);
            float s, c;
            sincospif((float)k * (float)(n - HALF) / 2048.0f, &s, &c);
            hr = fmaf(w, c, hr);
            hi = fmaf(w, s, hi);
        }
        g_H[k] = make_float2(hr * (1.0f / (float)NFFT), hi * (1.0f / (float)NFFT));
    }
}

// ---------------------------------------------------------------- 4-pt DFT in place
template<bool FWD>
__device__ __forceinline__ void dft4(float2& x0, float2& x1, float2& x2, float2& x3) {
    float2 apc = make_float2(x0.x + x2.x, x0.y + x2.y);
    float2 amc = make_float2(x0.x - x2.x, x0.y - x2.y);
    float2 bpd = make_float2(x1.x + x3.x, x1.y + x3.y);
    float2 bmd = make_float2(x1.x - x3.x, x1.y - x3.y);
    x0 = make_float2(apc.x + bpd.x, apc.y + bpd.y);
    x2 = make_float2(apc.x - bpd.x, apc.y - bpd.y);
    if (FWD) {
        x1 = make_float2(amc.x + bmd.y, amc.y - bmd.x);
        x3 = make_float2(amc.x - bmd.y, amc.y + bmd.x);
    } else {
        x1 = make_float2(amc.x - bmd.y, amc.y + bmd.x);
        x3 = make_float2(amc.x + bmd.y, amc.y - bmd.x);
    }
}

template<bool FWD>
__device__ __forceinline__ float2 twc(float2 a, float cr, float ci) {
    float s = FWD ? ci : -ci;
    return make_float2(fmaf(a.x, cr, -a.y * s), fmaf(a.x, s, a.y * cr));
}

#define C16 0.9238795325112867f
#define S16 0.3826834323650898f
#define RQ2 0.7071067811865476f
#define PI(q) ((((q) & 3) << 2) | ((q) >> 2))

// 16-pt DFT in registers; X[q] ends at a[PI(q)]
template<bool FWD>
__device__ __forceinline__ void dft16(float2* a) {
    dft4<FWD>(a[0], a[4], a[8],  a[12]);
    dft4<FWD>(a[1], a[5], a[9],  a[13]);
    dft4<FWD>(a[2], a[6], a[10], a[14]);
    dft4<FWD>(a[3], a[7], a[11], a[15]);
    a[5]  = twc<FWD>(a[5],   C16, -S16);
    a[9]  = twc<FWD>(a[9],   RQ2, -RQ2);
    a[13] = twc<FWD>(a[13],  S16, -C16);
    a[6]  = twc<FWD>(a[6],   RQ2, -RQ2);
    a[10] = twc<FWD>(a[10],  0.f, -1.f);
    a[14] = twc<FWD>(a[14], -RQ2, -RQ2);
    a[7]  = twc<FWD>(a[7],   S16, -C16);
    a[11] = twc<FWD>(a[11], -RQ2, -RQ2);
    a[15] = twc<FWD>(a[15], -C16,  S16);
    dft4<FWD>(a[0],  a[1],  a[2],  a[3]);
    dft4<FWD>(a[4],  a[5],  a[6],  a[7]);
    dft4<FWD>(a[8],  a[9],  a[10], a[11]);
    dft4<FWD>(a[12], a[13], a[14], a[15]);
}

// stride-256 register load: addr = pbase + 272p (immediate offsets)
__device__ __forceinline__ void fft_load(const float2* buf, int pbase, float2* a) {
    #pragma unroll
    for (int p = 0; p < 16; p++) a[p] = buf[pbase + 272 * p];
}

// twiddled store: addr = sbase + STEP*q (immediate offsets), twiddles w^q, w = g_twf[twidx]
// twiddle tree: w1,w2,w4,w8 persistent; w3,w5,w6,w7 transient (low live set)
template<bool FWD, int STEP>
__device__ __forceinline__ void fft_twstore(float2* buf, int sbase, int twidx, const float2* a) {
    float2 w1 = g_twf[twidx];
    if (!FWD) w1.y = -w1.y;
    float2 w2 = cmul(w1, w1);
    float2 w4 = cmul(w2, w2);
    float2 w8 = cmul(w4, w4);
    buf[sbase]             = a[0];
    buf[sbase + STEP]      = cmul(w1, a[4]);
    buf[sbase + 2*STEP]    = cmul(w2, a[8]);
    buf[sbase + 4*STEP]    = cmul(w4, a[1]);
    buf[sbase + 8*STEP]    = cmul(w8, a[2]);
    buf[sbase + 9*STEP]    = cmul(cmul(w8, w1), a[6]);
    buf[sbase + 10*STEP]   = cmul(cmul(w8, w2), a[10]);
    buf[sbase + 12*STEP]   = cmul(cmul(w8, w4), a[3]);
    {
        float2 w3 = cmul(w2, w1);
        buf[sbase + 3*STEP]  = cmul(w3, a[12]);
        buf[sbase + 11*STEP] = cmul(cmul(w8, w3), a[14]);
        float2 w7 = cmul(w4, w3);
        buf[sbase + 7*STEP]  = cmul(w7, a[13]);
        buf[sbase + 15*STEP] = cmul(cmul(w8, w7), a[15]);
    }
    {
        float2 w5 = cmul(w4, w1);
        buf[sbase + 5*STEP]  = cmul(w5, a[5]);
        buf[sbase + 13*STEP] = cmul(cmul(w8, w5), a[7]);
        float2 w6 = cmul(w4, w2);
        buf[sbase + 6*STEP]  = cmul(w6, a[9]);
        buf[sbase + 14*STEP] = cmul(cmul(w8, w6), a[11]);
    }
}

// select k[p] from 8 registers (p in 1..7; else 0), branch-free
__device__ __forceinline__ u64 sel8(const u64* k, int p) {
    u64 r = 0;
    r = (p == 1) ? k[1] : r;
    r = (p == 2) ? k[2] : r;
    r = (p == 3) ? k[3] : r;
    r = (p == 4) ? k[4] : r;
    r = (p == 5) ? k[5] : r;
    r = (p == 6) ? k[6] : r;
    r = (p == 7) ? k[7] : r;
    return r;
}

__device__ __forceinline__ u64 warp_max_u64(u64 v) {
    #pragma unroll
    for (int off = 16; off; off >>= 1) {
        u64 o = __shfl_xor_sync(0xffffffffu, v, off);
        if (o > v) v = o;
    }
    return v;
}

// sort 8 keys descending (19-comparator network)
__device__ __forceinline__ void sort8(u64* k) {
    #define CSW(i, j) do { if (k[i] < k[j]) { u64 _t = k[i]; k[i] = k[j]; k[j] = _t; } } while (0)
    CSW(0,1); CSW(2,3); CSW(4,5); CSW(6,7);
    CSW(0,2); CSW(1,3); CSW(4,6); CSW(5,7);
    CSW(1,2); CSW(5,6);
    CSW(0,4); CSW(1,5); CSW(2,6); CSW(3,7);
    CSW(2,4); CSW(3,5);
    CSW(1,2); CSW(3,4); CSW(5,6);
    #undef CSW
}

// warp-local top-16 of sorted per-thread lists -> warpTop[16]
__device__ __forceinline__ void warp_topk(const u64* k, u64* warpTopRow) {
    u64 c = k[0];
    int p = 1;
    #pragma unroll 1
    for (int it = 0; it < KTOP; it++) {
        u64 w = warp_max_u64(c);
        if (c == w) {
            warpTopRow[it] = w;
            c = sel8(k, p); p++;
        }
    }
}

// ---------------------------------------------------------------- fused kernel
__global__ void __launch_bounds__(THR, 5) spectral_kernel(const float* __restrict__ x,
                                                          float* __restrict__ out) {
    extern __shared__ float2 buf[];                 // BUFSZ float2
    __shared__ u64    warpTop[2][8][KTOP];
    __shared__ int    sIdx[2][KTOP];
    __shared__ float2 sVal[2][KTOP];
    __shared__ float  sraw[2][48];
    __shared__ float  swt[WIN];

    const int tid  = threadIdx.x & 255;             // range-known for addr folding
    const int wid  = tid >> 5;
    const int lane = tid & 31;
    const int hi4  = tid >> 4;
    const int pbase  = tid + hi4;                   // PAD(tid)
    const int s0base = 17 * tid;                    // stage-0 store base (+q)
    const int s1base = 272 * hi4 + (tid & 15);      // stage-1 store base (+17q)
    const int P = blockIdx.x;
    const int b = P >> 6;
    const int f = (P & 63) * 2;
    const float* xin   = x   + (size_t)b * TLEN * NF + f;
    float*       obase = out + (size_t)b * TLEN * NF + f;

    if (tid < WIN)
        swt[tid] = (0.54f - 0.46f * cospif(2.0f * (float)tid / 25.0f)) * (1.0f / 13.5f);

    // ================= forward FFT =================
    float2 a[16];
    #pragma unroll
    for (int p = 0; p < 16; p++)
        a[p] = *(const float2*)(xin + (size_t)(tid + 256 * p) * NF);
    dft16<true>(a);
    fft_twstore<true, 1>(buf, s0base, tid, a);
    __syncthreads();
    fft_load(buf, pbase, a);
    __syncthreads();
    dft16<true>(a);
    fft_twstore<true, 17>(buf, s1base, tid & ~15, a);
    __syncthreads();
    fft_load(buf, pbase, a);
    __syncthreads();
    dft16<true>(a);
    #pragma unroll
    for (int q = 0; q < 16; q++) buf[pbase + 272 * q] = a[PI(q)];   // stage-2 plain store
    __syncthreads();

    // ---- top-k, series A (z from regs, partner from smem), then series B (both from smem)
    // key = mag_bits<<12 | (4095-m): unique; order == lax.top_k (ties -> lower m)
    {
        u64 kk[8];
        #pragma unroll
        for (int k = 0; k < 8; k++) {
            int m = tid + k * THR;
            float2 z  = a[PI(k)];
            int pm = (NFFT - m) & (NFFT - 1);
            float2 zm = buf[PAD(pm)];
            float ar = z.x + zm.x, ai = z.y - zm.y;     // 2*A[m]
            float mag = fmaf(ar, ar, ai * ai);
            kk[k] = ((u64)__float_as_uint(mag) << 12) | (unsigned)(4095 - m);
        }
        sort8(kk);
        warp_topk(kk, warpTop[0][wid]);
        #pragma unroll
        for (int k = 0; k < 8; k++) {
            int m = tid + k * THR;
            float2 z  = buf[pbase + 272 * k];
            int pm = (NFFT - m) & (NFFT - 1);
            float2 zm = buf[PAD(pm)];
            float br = z.y + zm.y, bi = zm.x - z.x;      // 2*B[m]
            float mag = fmaf(br, br, bi * bi);
            kk[k] = ((u64)__float_as_uint(mag) << 12) | (unsigned)(4095 - m);
        }
        sort8(kk);
        warp_topk(kk, warpTop[1][wid]);
    }
    __syncthreads();

    // ---- CTA merge: warp 0 -> series A, warp 1 -> series B; lane 8 = bin-2048 singleton
    if (wid < 2) {
        const int s = wid;
        u64 cand = 0;
        int p = 1;
        if (lane < 8) cand = warpTop[s][lane][0];
        else if (lane == 8) {
            float2 z = buf[PAD(2048)];
            float mag = (s == 0) ? 4.f * z.x * z.x : 4.f * z.y * z.y;
            cand = ((u64)__float_as_uint(mag) << 12) | (unsigned)(4095 - 2048);
        }
        #pragma unroll 1
        for (int it = 0; it < KTOP; it++) {
            u64 win = warp_max_u64(cand);
            if (cand == win) {
                int m = 4095 - (int)(win & 0xFFFu);
                float2 z  = buf[PAD(m)];
                float2 zm = buf[PAD((NFFT - m) & (NFFT - 1))];
                sIdx[s][it] = m;
                sVal[s][it] = (s == 0)
                    ? make_float2(0.5f * (z.x + zm.x), 0.5f * (z.y - zm.y))
                    : make_float2(0.5f * (z.y + zm.y), 0.5f * (zm.x - z.x));
                if (lane < 8) { cand = (p < KTOP) ? warpTop[s][lane][p] : 0; p++; }
                else cand = 0;
            }
        }
    }
    __syncthreads();

    // zero buffer; low threads compute raw edge values from the kept bins
    #pragma unroll
    for (int u = 0; u < 16; u++)
        buf[pbase + 272 * u] = make_float2(0.f, 0.f);
    if (tid < 96) {
        int srs = tid & 1, pos = tid >> 1;
        int t = pos < 24 ? pos : TLEN - 48 + pos;
        float acc = 0.f;
        #pragma unroll
        for (int j = 0; j < KTOP; j++) {
            int m = sIdx[srs][j];
            float2 v = sVal[srs][j];
            float2 tw = g_twf[(m * t) & (NFFT - 1)];
            float coef = (m == 0 || m == 2048) ? 1.f : 2.f;
            acc = fmaf(coef * v.x, tw.x, acc);
            acc = fmaf(coef * v.y, tw.y, acc);
        }
        sraw[srs][pos] = acc * (1.0f / (float)NFFT);
    }
    __syncthreads();

    // scatter filtered bins (H carries 1/NFFT): series a
    if (tid < KTOP) {
        int m = sIdx[0][tid];
        float2 vf = cmul(sVal[0][tid], g_H[m]);
        buf[PAD(m)] = vf;
        if (m > 0 && m < 2048) buf[PAD(NFFT - m)] = make_float2(vf.x, -vf.y);
    }
    __syncthreads();
    // series b (additive, times i)
    if (tid < KTOP) {
        int m = sIdx[1][tid];
        float2 wf = cmul(sVal[1][tid], g_H[m]);
        float2 c = buf[PAD(m)];
        c.x -= wf.y; c.y += wf.x;
        buf[PAD(m)] = c;
        if (m > 0 && m < 2048) {
            float2 c2 = buf[PAD(NFFT - m)];
            c2.x += wf.y; c2.y += wf.x;
            buf[PAD(NFFT - m)] = c2;
        }
    }
    __syncthreads();

    // ================= inverse FFT: stages 0,1 in smem; stage 2 -> gmem =================
    fft_load(buf, pbase, a);
    __syncthreads();
    dft16<false>(a);
    fft_twstore<false, 1>(buf, s0base, tid, a);
    __syncthreads();
    fft_load(buf, pbase, a);
    __syncthreads();
    dft16<false>(a);
    fft_twstore<false, 17>(buf, s1base, tid & ~15, a);
    __syncthreads();
    fft_load(buf, pbase, a);
    dft16<false>(a);
    #pragma unroll
    for (int q = 0; q < 16; q++) {
        int t = tid + 256 * q;
        bool interior = true;
        if (q == 0)  interior = (tid >= HALF);
        if (q == 15) interior = (tid < 256 - HALF);
        if (interior)
            *(float2*)(obase + (size_t)t * NF) = a[PI(q)];
    }

    // exact edge outputs via flip-padded direct convolution of raw values
    if (tid < 48) {
        int srs = tid & 1, j = tid >> 1;
        float acc = 0.f;
        if (j < 12) {
            #pragma unroll
            for (int n = 0; n < WIN; n++) {
                int q = j + n - HALF;
                q = q < 0 ? -1 - q : q;
                acc = fmaf(swt[n], sraw[srs][q], acc);
            }
            obase[(size_t)j * NF + srs] = acc;
        } else {
            int e = j - 12;
            #pragma unroll
            for (int n = 0; n < WIN; n++) {
                int q = e + n;
                int loc = q < 24 ? q : 47 - q;
                acc = fmaf(swt[n], sraw[srs][24 + loc], acc);
            }
            obase[(size_t)(TLEN - 12 + e) * NF + srs] = acc;
        }
    }
}

// ---------------------------------------------------------------- launch
extern "C" void kernel_launch(void* const* d_in, const int* in_sizes, int n_in,
                              void* d_out, int out_size) {
    const float* x = (const float*)d_in[0];
    float* out = (float*)d_out;

    size_t smem = BUFSZ * sizeof(float2);   // 34816 B dynamic
    init_kernel<<<16, 256>>>();
    spectral_kernel<<<NB * NF / 2, THR, smem>>>(x, out);
}

// round 15
// speedup vs baseline: 1.1456x; 1.1456x over previous
#include <cuda_runtime.h>

#define NB    32
#define TLEN  4096
#define NF    128
#define NFFT  4096
#define KTOP  16
#define WIN   25
#define HALF  12
#define THR   256
#define BUFSZ 4352
#define PAD(i) ((i) + ((i) >> 4))

typedef unsigned long long u64;
typedef unsigned int u32;

__device__ float2 g_twf[NFFT];                    // e^{-2pi i k / 4096}
__device__ float2 g_H[NFFT/2 + 1];                // Hamming freq response * (1/4096)

__device__ __forceinline__ float2 cmul(float2 a, float2 b) {
    return make_float2(fmaf(a.x, b.x, -a.y * b.y), fmaf(a.x, b.y, a.y * b.x));
}

// ---------------------------------------------------------------- init
__global__ void init_kernel() {
    int k = blockIdx.x * blockDim.x + threadIdx.x;
    if (k < NFFT) {
        double a = -(double)k / 2048.0;
        g_twf[k] = make_float2((float)cospi(a), (float)sinpi(a));
    }
    if (k <= NFFT/2) {
        float hr = 0.f, hi = 0.f;
        #pragma unroll 1
        for (int n = 0; n < WIN; n++) {
            float w = (0.54f - 0.46f * cospif(2.0f * (float)n / 25.0f)) * (1.0f / 13.5f);
            float s, c;
            sincospif((float)k * (float)(n - HALF) / 2048.0f, &s, &c);
            hr = fmaf(w, c, hr);
            hi = fmaf(w, s, hi);
        }
        g_H[k] = make_float2(hr * (1.0f / (float)NFFT), hi * (1.0f / (float)NFFT));
    }
}

// ---------------------------------------------------------------- 4-pt DFT in place
template<bool FWD>
__device__ __forceinline__ void dft4(float2& x0, float2& x1, float2& x2, float2& x3) {
    float2 apc = make_float2(x0.x + x2.x, x0.y + x2.y);
    float2 amc = make_float2(x0.x - x2.x, x0.y - x2.y);
    float2 bpd = make_float2(x1.x + x3.x, x1.y + x3.y);
    float2 bmd = make_float2(x1.x - x3.x, x1.y - x3.y);
    x0 = make_float2(apc.x + bpd.x, apc.y + bpd.y);
    x2 = make_float2(apc.x - bpd.x, apc.y - bpd.y);
    if (FWD) {
        x1 = make_float2(amc.x + bmd.y, amc.y - bmd.x);
        x3 = make_float2(amc.x - bmd.y, amc.y + bmd.x);
    } else {
        x1 = make_float2(amc.x - bmd.y, amc.y + bmd.x);
        x3 = make_float2(amc.x + bmd.y, amc.y - bmd.x);
    }
}

template<bool FWD>
__device__ __forceinline__ float2 twc(float2 a, float cr, float ci) {
    float s = FWD ? ci : -ci;
    return make_float2(fmaf(a.x, cr, -a.y * s), fmaf(a.x, s, a.y * cr));
}

#define C16 0.9238795325112867f
#define S16 0.3826834323650898f
#define RQ2 0.7071067811865476f
#define PI(q) ((((q) & 3) << 2) | ((q) >> 2))

// 16-pt DFT in registers; X[q] ends at a[PI(q)]
template<bool FWD>
__device__ __forceinline__ void dft16(float2* a) {
    dft4<FWD>(a[0], a[4], a[8],  a[12]);
    dft4<FWD>(a[1], a[5], a[9],  a[13]);
    dft4<FWD>(a[2], a[6], a[10], a[14]);
    dft4<FWD>(a[3], a[7], a[11], a[15]);
    a[5]  = twc<FWD>(a[5],   C16, -S16);
    a[9]  = twc<FWD>(a[9],   RQ2, -RQ2);
    a[13] = twc<FWD>(a[13],  S16, -C16);
    a[6]  = twc<FWD>(a[6],   RQ2, -RQ2);
    a[10] = twc<FWD>(a[10],  0.f, -1.f);
    a[14] = twc<FWD>(a[14], -RQ2, -RQ2);
    a[7]  = twc<FWD>(a[7],   S16, -C16);
    a[11] = twc<FWD>(a[11], -RQ2, -RQ2);
    a[15] = twc<FWD>(a[15], -C16,  S16);
    dft4<FWD>(a[0],  a[1],  a[2],  a[3]);
    dft4<FWD>(a[4],  a[5],  a[6],  a[7]);
    dft4<FWD>(a[8],  a[9],  a[10], a[11]);
    dft4<FWD>(a[12], a[13], a[14], a[15]);
}

// stride-256 register load: addr = pbase + 272p (immediate offsets)
__device__ __forceinline__ void fft_load(const float2* buf, int pbase, float2* a) {
    #pragma unroll
    for (int p = 0; p < 16; p++) a[p] = buf[pbase + 272 * p];
}

// twiddled store: addr = sbase + STEP*q (immediate offsets), twiddles w^q, w = g_twf[twidx]
template<bool FWD, int STEP>
__device__ __forceinline__ void fft_twstore(float2* buf, int sbase, int twidx, const float2* a) {
    float2 w1 = g_twf[twidx];
    if (!FWD) w1.y = -w1.y;
    float2 w2 = cmul(w1, w1);
    float2 w4 = cmul(w2, w2);
    float2 w8 = cmul(w4, w4);
    buf[sbase]             = a[0];
    buf[sbase + STEP]      = cmul(w1, a[4]);
    buf[sbase + 2*STEP]    = cmul(w2, a[8]);
    buf[sbase + 4*STEP]    = cmul(w4, a[1]);
    buf[sbase + 8*STEP]    = cmul(w8, a[2]);
    buf[sbase + 9*STEP]    = cmul(cmul(w8, w1), a[6]);
    buf[sbase + 10*STEP]   = cmul(cmul(w8, w2), a[10]);
    buf[sbase + 12*STEP]   = cmul(cmul(w8, w4), a[3]);
    {
        float2 w3 = cmul(w2, w1);
        buf[sbase + 3*STEP]  = cmul(w3, a[12]);
        buf[sbase + 11*STEP] = cmul(cmul(w8, w3), a[14]);
        float2 w7 = cmul(w4, w3);
        buf[sbase + 7*STEP]  = cmul(w7, a[13]);
        buf[sbase + 15*STEP] = cmul(cmul(w8, w7), a[15]);
    }
    {
        float2 w5 = cmul(w4, w1);
        buf[sbase + 5*STEP]  = cmul(w5, a[5]);
        buf[sbase + 13*STEP] = cmul(cmul(w8, w5), a[7]);
        float2 w6 = cmul(w4, w2);
        buf[sbase + 6*STEP]  = cmul(w6, a[9]);
        buf[sbase + 14*STEP] = cmul(cmul(w8, w6), a[11]);
    }
}

// select k[p] from 8 registers (p in 1..7; else 0), branch-free
__device__ __forceinline__ u64 sel8(const u64* k, int p) {
    u64 r = 0;
    r = (p == 1) ? k[1] : r;
    r = (p == 2) ? k[2] : r;
    r = (p == 3) ? k[3] : r;
    r = (p == 4) ? k[4] : r;
    r = (p == 5) ? k[5] : r;
    r = (p == 6) ? k[6] : r;
    r = (p == 7) ? k[7] : r;
    return r;
}

// warp max of split key (mag32, enc12) via 2x REDUX; bit-exact == u64 max of mag<<12|enc
__device__ __forceinline__ u64 warp_max_key(u64 cand) {
    u32 mag  = (u32)(cand >> 12);
    u32 wmag = __reduce_max_sync(0xffffffffu, mag);
    u32 enc  = (mag == wmag) ? (u32)(cand & 0xFFFu) : 0u;
    u32 wenc = __reduce_max_sync(0xffffffffu, enc);
    return ((u64)wmag << 12) | wenc;
}

// sort 8 keys descending (19-comparator network)
__device__ __forceinline__ void sort8(u64* k) {
    #define CSW(i, j) do { if (k[i] < k[j]) { u64 _t = k[i]; k[i] = k[j]; k[j] = _t; } } while (0)
    CSW(0,1); CSW(2,3); CSW(4,5); CSW(6,7);
    CSW(0,2); CSW(1,3); CSW(4,6); CSW(5,7);
    CSW(1,2); CSW(5,6);
    CSW(0,4); CSW(1,5); CSW(2,6); CSW(3,7);
    CSW(2,4); CSW(3,5);
    CSW(1,2); CSW(3,4); CSW(5,6);
    #undef CSW
}

// warp-local top-16 of sorted per-thread lists -> warpTopRow[16]
__device__ __forceinline__ void warp_topk(const u64* k, u64* warpTopRow) {
    u64 c = k[0];
    int p = 1;
    #pragma unroll 1
    for (int it = 0; it < KTOP; it++) {
        u64 w = warp_max_key(c);
        if (c == w) {                 // exactly one lane (keys unique)
            warpTopRow[it] = w;
            c = sel8(k, p); p++;
        }
    }
}

// ---------------------------------------------------------------- fused kernel
__global__ void __launch_bounds__(THR, 5) spectral_kernel(const float* __restrict__ x,
                                                          float* __restrict__ out) {
    extern __shared__ float2 buf[];                 // BUFSZ float2
    __shared__ u64    warpTop[2][8][KTOP];
    __shared__ int    sIdx[2][KTOP];
    __shared__ float2 sVal[2][KTOP];
    __shared__ float  sraw[2][48];
    __shared__ float  swt[WIN];

    const int tid  = threadIdx.x & 255;             // range-known for addr folding
    const int wid  = tid >> 5;
    const int lane = tid & 31;
    const int hi4  = tid >> 4;
    const int pbase  = tid + hi4;                   // PAD(tid)
    const int s0base = 17 * tid;                    // stage-0 store base (+q)
    const int s1base = 272 * hi4 + (tid & 15);      // stage-1 store base (+17q)
    const int P = blockIdx.x;
    const int b = P >> 6;
    const int f = (P & 63) * 2;
    const float* xin   = x   + (size_t)b * TLEN * NF + f;
    float*       obase = out + (size_t)b * TLEN * NF + f;

    if (tid < WIN)
        swt[tid] = (0.54f - 0.46f * cospif(2.0f * (float)tid / 25.0f)) * (1.0f / 13.5f);

    // ================= forward FFT =================
    float2 a[16];
    #pragma unroll
    for (int p = 0; p < 16; p++)
        a[p] = *(const float2*)(xin + (size_t)(tid + 256 * p) * NF);
    dft16<true>(a);
    fft_twstore<true, 1>(buf, s0base, tid, a);
    __syncthreads();
    fft_load(buf, pbase, a);
    __syncthreads();
    dft16<true>(a);
    fft_twstore<true, 17>(buf, s1base, tid & ~15, a);
    __syncthreads();
    fft_load(buf, pbase, a);
    __syncthreads();
    dft16<true>(a);
    #pragma unroll
    for (int q = 0; q < 16; q++) buf[pbase + 272 * q] = a[PI(q)];   // stage-2 plain store
    __syncthreads();

    // ---- top-k: series A (z from regs), then series B (z from smem)
    // key = mag_bits<<12 | (4095-m): unique; order == lax.top_k (ties -> lower m)
    {
        u64 kk[8];
        #pragma unroll
        for (int k = 0; k < 8; k++) {
            int m = tid + k * THR;
            float2 z  = a[PI(k)];
            float2 zm = buf[PAD((NFFT - m) & (NFFT - 1))];
            float ar = z.x + zm.x, ai = z.y - zm.y;     // 2*A[m]
            float mag = fmaf(ar, ar, ai * ai);
            kk[k] = ((u64)__float_as_uint(mag) << 12) | (unsigned)(4095 - m);
        }
        sort8(kk);
        warp_topk(kk, warpTop[0][wid]);
        #pragma unroll
        for (int k = 0; k < 8; k++) {
            int m = tid + k * THR;
            float2 z  = buf[pbase + 272 * k];
            float2 zm = buf[PAD((NFFT - m) & (NFFT - 1))];
            float br = z.y + zm.y, bi = zm.x - z.x;      // 2*B[m]
            float mag = fmaf(br, br, bi * bi);
            kk[k] = ((u64)__float_as_uint(mag) << 12) | (unsigned)(4095 - m);
        }
        sort8(kk);
        warp_topk(kk, warpTop[1][wid]);
    }
    __syncthreads();

    // ---- CTA merge: warp 0 -> series A, warp 1 -> series B; lane 8 = bin-2048 singleton
    if (wid < 2) {
        const int s = wid;
        u64 cand = 0;
        int p = 1;
        if (lane < 8) cand = warpTop[s][lane][0];
        else if (lane == 8) {
            float2 z = buf[PAD(2048)];
            float mag = (s == 0) ? 4.f * z.x * z.x : 4.f * z.y * z.y;
            cand = ((u64)__float_as_uint(mag) << 12) | (unsigned)(4095 - 2048);
        }
        #pragma unroll 1
        for (int it = 0; it < KTOP; it++) {
            u64 win = warp_max_key(cand);
            if (cand == win) {
                int m = 4095 - (int)(win & 0xFFFu);
                float2 z  = buf[PAD(m)];
                float2 zm = buf[PAD((NFFT - m) & (NFFT - 1))];
                sIdx[s][it] = m;
                sVal[s][it] = (s == 0)
                    ? make_float2(0.5f * (z.x + zm.x), 0.5f * (z.y - zm.y))
                    : make_float2(0.5f * (z.y + zm.y), 0.5f * (zm.x - z.x));
                if (lane < 8) { cand = (p < KTOP) ? warpTop[s][lane][p] : 0; p++; }
                else cand = 0;
            }
        }
    }
    __syncthreads();

    // zero buffer; low threads compute raw edge values from the kept bins
    #pragma unroll
    for (int u = 0; u < 16; u++)
        buf[pbase + 272 * u] = make_float2(0.f, 0.f);
    if (tid < 96) {
        int srs = tid & 1, pos = tid >> 1;
        int t = pos < 24 ? pos : TLEN - 48 + pos;
        float acc = 0.f;
        #pragma unroll
        for (int j = 0; j < KTOP; j++) {
            int m = sIdx[srs][j];
            float2 v = sVal[srs][j];
            float2 tw = g_twf[(m * t) & (NFFT - 1)];
            float coef = (m == 0 || m == 2048) ? 1.f : 2.f;
            acc = fmaf(coef * v.x, tw.x, acc);
            acc = fmaf(coef * v.y, tw.y, acc);
        }
        sraw[srs][pos] = acc * (1.0f / (float)NFFT);
    }
    __syncthreads();

    // scatter filtered bins (H carries 1/NFFT): warp 0 does series a, then b (syncwarp between)
    if (wid == 0) {
        if (lane < KTOP) {
            int m = sIdx[0][lane];
            float2 vf = cmul(sVal[0][lane], g_H[m]);
            buf[PAD(m)] = vf;
            if (m > 0 && m < 2048) buf[PAD(NFFT - m)] = make_float2(vf.x, -vf.y);
        }
        __syncwarp();
        if (lane < KTOP) {
            int m = sIdx[1][lane];
            float2 wf = cmul(sVal[1][lane], g_H[m]);
            float2 c = buf[PAD(m)];
            c.x -= wf.y; c.y += wf.x;
            buf[PAD(m)] = c;
            if (m > 0 && m < 2048) {
                float2 c2 = buf[PAD(NFFT - m)];
                c2.x += wf.y; c2.y += wf.x;
                buf[PAD(NFFT - m)] = c2;
            }
        }
    }
    __syncthreads();

    // ================= inverse FFT: stages 0,1 in smem; stage 2 -> gmem =================
    fft_load(buf, pbase, a);
    __syncthreads();
    dft16<false>(a);
    fft_twstore<false, 1>(buf, s0base, tid, a);
    __syncthreads();
    fft_load(buf, pbase, a);
    __syncthreads();
    dft16<false>(a);
    fft_twstore<false, 17>(buf, s1base, tid & ~15, a);
    __syncthreads();
    fft_load(buf, pbase, a);
    dft16<false>(a);
    #pragma unroll
    for (int q = 0; q < 16; q++) {
        int t = tid + 256 * q;
        bool interior = true;
        if (q == 0)  interior = (tid >= HALF);
        if (q == 15) interior = (tid < 256 - HALF);
        if (interior)
            *(float2*)(obase + (size_t)t * NF) = a[PI(q)];
    }

    // exact edge outputs via flip-padded direct convolution of raw values
    if (tid < 48) {
        int srs = tid & 1, j = tid >> 1;
        float acc = 0.f;
        if (j < 12) {
            #pragma unroll
            for (int n = 0; n < WIN; n++) {
                int q = j + n - HALF;
                q = q < 0 ? -1 - q : q;
                acc = fmaf(swt[n], sraw[srs][q], acc);
            }
            obase[(size_t)j * NF + srs] = acc;
        } else {
            int e = j - 12;
            #pragma unroll
            for (int n = 0; n < WIN; n++) {
                int q = e + n;
                int loc = q < 24 ? q : 47 - q;
                acc = fmaf(swt[n], sraw[srs][24 + loc], acc);
            }
            obase[(size_t)(TLEN - 12 + e) * NF + srs] = acc;
        }
    }
}

// ---------------------------------------------------------------- launch
extern "C" void kernel_launch(void* const* d_in, const int* in_sizes, int n_in,
                              void* d_out, int out_size) {
    const float* x = (const float*)d_in[0];
    float* out = (float*)d_out;

    size_t smem = BUFSZ * sizeof(float2);   // 34816 B dynamic
    init_kernel<<<16, 256>>>();
    spectral_kernel<<<NB * NF / 2, THR, smem>>>(x, out);
}

// round 16
// speedup vs baseline: 1.1851x; 1.0345x over previous
#include <cuda_runtime.h>

#define NB    32
#define TLEN  4096
#define NF    128
#define NFFT  4096
#define KTOP  16
#define WIN   25
#define HALF  12
#define THR   256
#define BUFSZ 4352
#define PAD(i) ((i) + ((i) >> 4))

typedef unsigned long long u64;
typedef unsigned int u32;

__device__ float2 g_twf[NFFT];                    // e^{-2pi i k / 4096}
__device__ float2 g_H[NFFT/2 + 1];                // Hamming freq response * (1/4096)

__device__ __forceinline__ float2 cmul(float2 a, float2 b) {
    return make_float2(fmaf(a.x, b.x, -a.y * b.y), fmaf(a.x, b.y, a.y * b.x));
}

// ---------------------------------------------------------------- packed f32x2 helpers
__device__ __forceinline__ u64 F2U(float2 v) { union { float2 f; u64 u; } c; c.f = v; return c.u; }
__device__ __forceinline__ float2 U2F(u64 u) { union { float2 f; u64 u; } c; c.u = u; return c.f; }

__device__ __forceinline__ float2 padd(float2 a, float2 b) {
    u64 r, x = F2U(a), y = F2U(b);
    asm("add.rn.f32x2 %0, %1, %2;" : "=l"(r) : "l"(x), "l"(y));
    return U2F(r);
}
// a - b == fma(b, -1, a); exact
__device__ __forceinline__ float2 psub(float2 a, float2 b) {
    u64 r, x = F2U(a), y = F2U(b);
    const u64 NEG1 = 0xBF800000BF800000ULL;
    asm("fma.rn.f32x2 %0, %1, %2, %3;" : "=l"(r) : "l"(y), "l"(NEG1), "l"(x));
    return U2F(r);
}
__device__ __forceinline__ float2 pmul(float2 a, float2 b) {
    u64 r, x = F2U(a), y = F2U(b);
    asm("mul.rn.f32x2 %0, %1, %2;" : "=l"(r) : "l"(x), "l"(y));
    return U2F(r);
}
__device__ __forceinline__ float2 pfma(float2 a, float2 b, float2 c) {
    u64 r, x = F2U(a), y = F2U(b), z = F2U(c);
    asm("fma.rn.f32x2 %0, %1, %2, %3;" : "=l"(r) : "l"(x), "l"(y), "l"(z));
    return U2F(r);
}

// ---------------------------------------------------------------- init
__global__ void init_kernel() {
    int k = blockIdx.x * blockDim.x + threadIdx.x;
    if (k < NFFT) {
        double a = -(double)k / 2048.0;
        g_twf[k] = make_float2((float)cospi(a), (float)sinpi(a));
    }
    if (k <= NFFT/2) {
        float hr = 0.f, hi = 0.f;
        #pragma unroll 1
        for (int n = 0; n < WIN; n++) {
            float w = (0.54f - 0.46f * cospif(2.0f * (float)n / 25.0f)) * (1.0f / 13.5f);
            float s, c;
            sincospif((float)k * (float)(n - HALF) / 2048.0f, &s, &c);
            hr = fmaf(w, c, hr);
            hi = fmaf(w, s, hi);
        }
        g_H[k] = make_float2(hr * (1.0f / (float)NFFT), hi * (1.0f / (float)NFFT));
    }
}

// ---------------------------------------------------------------- 4-pt DFT in place (packed)
template<bool FWD>
__device__ __forceinline__ void dft4(float2& x0, float2& x1, float2& x2, float2& x3) {
    float2 apc = padd(x0, x2);
    float2 amc = psub(x0, x2);
    float2 bpd = padd(x1, x3);
    float2 bmd = psub(x1, x3);
    x0 = padd(apc, bpd);
    x2 = psub(apc, bpd);
    float2 sw = FWD ? make_float2(bmd.y, -bmd.x) : make_float2(-bmd.y, bmd.x);
    x1 = padd(amc, sw);
    x3 = psub(amc, sw);
}

// const-twiddle cmul: r = (a.x*c - a.y*s, a.y*c + a.x*s), packed: pmul + neg + pfma
template<bool FWD>
__device__ __forceinline__ float2 twc(float2 a, float cr, float ci) {
    float s = FWD ? ci : -ci;
    float2 p   = pmul(a, make_float2(cr, cr));
    float2 asn = make_float2(-a.y, a.x);
    return pfma(asn, make_float2(s, s), p);
}

#define C16 0.9238795325112867f
#define S16 0.3826834323650898f
#define RQ2 0.7071067811865476f
#define PI(q) ((((q) & 3) << 2) | ((q) >> 2))

// 16-pt DFT in registers; X[q] ends at a[PI(q)]
template<bool FWD>
__device__ __forceinline__ void dft16(float2* a) {
    dft4<FWD>(a[0], a[4], a[8],  a[12]);
    dft4<FWD>(a[1], a[5], a[9],  a[13]);
    dft4<FWD>(a[2], a[6], a[10], a[14]);
    dft4<FWD>(a[3], a[7], a[11], a[15]);
    a[5]  = twc<FWD>(a[5],   C16, -S16);
    a[9]  = twc<FWD>(a[9],   RQ2, -RQ2);
    a[13] = twc<FWD>(a[13],  S16, -C16);
    a[6]  = twc<FWD>(a[6],   RQ2, -RQ2);
    a[10] = twc<FWD>(a[10],  0.f, -1.f);
    a[14] = twc<FWD>(a[14], -RQ2, -RQ2);
    a[7]  = twc<FWD>(a[7],   S16, -C16);
    a[11] = twc<FWD>(a[11], -RQ2, -RQ2);
    a[15] = twc<FWD>(a[15], -C16,  S16);
    dft4<FWD>(a[0],  a[1],  a[2],  a[3]);
    dft4<FWD>(a[4],  a[5],  a[6],  a[7]);
    dft4<FWD>(a[8],  a[9],  a[10], a[11]);
    dft4<FWD>(a[12], a[13], a[14], a[15]);
}

// stride-256 register load: addr = pbase + 272p (immediate offsets)
__device__ __forceinline__ void fft_load(const float2* buf, int pbase, float2* a) {
    #pragma unroll
    for (int p = 0; p < 16; p++) a[p] = buf[pbase + 272 * p];
}

// twiddled store: addr = sbase + STEP*q (immediate offsets), twiddles w^q, w = g_twf[twidx]
template<bool FWD, int STEP>
__device__ __forceinline__ void fft_twstore(float2* buf, int sbase, int twidx, const float2* a) {
    float2 w1 = g_twf[twidx];
    if (!FWD) w1.y = -w1.y;
    float2 w2 = cmul(w1, w1);
    float2 w4 = cmul(w2, w2);
    float2 w8 = cmul(w4, w4);
    buf[sbase]             = a[0];
    buf[sbase + STEP]      = cmul(w1, a[4]);
    buf[sbase + 2*STEP]    = cmul(w2, a[8]);
    buf[sbase + 4*STEP]    = cmul(w4, a[1]);
    buf[sbase + 8*STEP]    = cmul(w8, a[2]);
    buf[sbase + 9*STEP]    = cmul(cmul(w8, w1), a[6]);
    buf[sbase + 10*STEP]   = cmul(cmul(w8, w2), a[10]);
    buf[sbase + 12*STEP]   = cmul(cmul(w8, w4), a[3]);
    {
        float2 w3 = cmul(w2, w1);
        buf[sbase + 3*STEP]  = cmul(w3, a[12]);
        buf[sbase + 11*STEP] = cmul(cmul(w8, w3), a[14]);
        float2 w7 = cmul(w4, w3);
        buf[sbase + 7*STEP]  = cmul(w7, a[13]);
        buf[sbase + 15*STEP] = cmul(cmul(w8, w7), a[15]);
    }
    {
        float2 w5 = cmul(w4, w1);
        buf[sbase + 5*STEP]  = cmul(w5, a[5]);
        buf[sbase + 13*STEP] = cmul(cmul(w8, w5), a[7]);
        float2 w6 = cmul(w4, w2);
        buf[sbase + 6*STEP]  = cmul(w6, a[9]);
        buf[sbase + 14*STEP] = cmul(cmul(w8, w6), a[11]);
    }
}

// select k[p] from 8 registers (p in 1..7; else 0), branch-free
__device__ __forceinline__ u32 sel8u(const u32* k, int p) {
    u32 r = 0;
    r = (p == 1) ? k[1] : r;
    r = (p == 2) ? k[2] : r;
    r = (p == 3) ? k[3] : r;
    r = (p == 4) ? k[4] : r;
    r = (p == 5) ? k[5] : r;
    r = (p == 6) ? k[6] : r;
    r = (p == 7) ? k[7] : r;
    return r;
}

// sort 8 (mag, enc) pairs descending by mag (19-comparator network); enc rides along
__device__ __forceinline__ void sort8(u32* m, u32* e) {
    #define CSW(i, j) do { \
        bool _p = m[i] < m[j]; \
        u32 _hi = _p ? m[j] : m[i]; u32 _lo = _p ? m[i] : m[j]; \
        u32 _eh = _p ? e[j] : e[i]; u32 _el = _p ? e[i] : e[j]; \
        m[i] = _hi; m[j] = _lo; e[i] = _eh; e[j] = _el; \
    } while (0)
    CSW(0,1); CSW(2,3); CSW(4,5); CSW(6,7);
    CSW(0,2); CSW(1,3); CSW(4,6); CSW(5,7);
    CSW(1,2); CSW(5,6);
    CSW(0,4); CSW(1,5); CSW(2,6); CSW(3,7);
    CSW(2,4); CSW(3,5);
    CSW(1,2); CSW(3,4); CSW(5,6);
    #undef CSW
}

// warp-local top-16 of sorted per-thread lists (split-key REDUX max; enc tie-break = lower m)
__device__ __forceinline__ void warp_topk(const u32* mg, const u32* en, u32* topM, u32* topE) {
    u32 cm = mg[0], ce = en[0];
    int p = 1;
    #pragma unroll 1
    for (int it = 0; it < KTOP; it++) {
        u32 wm = __reduce_max_sync(0xffffffffu, cm);
        u32 we = __reduce_max_sync(0xffffffffu, (cm == wm) ? ce : 0u);
        if (cm == wm && ce == we) {            // exactly one lane (encs unique)
            topM[it] = wm; topE[it] = we;
            cm = sel8u(mg, p); ce = sel8u(en, p); p++;
        }
    }
}

// ---------------------------------------------------------------- fused kernel
__global__ void __launch_bounds__(THR, 5) spectral_kernel(const float* __restrict__ x,
                                                          float* __restrict__ out) {
    extern __shared__ float2 buf[];                 // BUFSZ float2
    __shared__ u32    warpTopM[2][8][KTOP], warpTopE[2][8][KTOP];
    __shared__ int    sIdx[2][KTOP];
    __shared__ float2 sVal[2][KTOP];
    __shared__ float  sraw[2][48];
    __shared__ float  swt[WIN];

    const int tid  = threadIdx.x & 255;             // range-known for addr folding
    const int wid  = tid >> 5;
    const int lane = tid & 31;
    const int hi4  = tid >> 4;
    const int pbase  = tid + hi4;                   // PAD(tid)
    const int s0base = 17 * tid;                    // stage-0 store base (+q)
    const int s1base = 272 * hi4 + (tid & 15);      // stage-1 store base (+17q)
    const int P = blockIdx.x;
    const int b = P >> 6;
    const int f = (P & 63) * 2;
    const float* xin   = x   + (size_t)b * TLEN * NF + f;
    float*       obase = out + (size_t)b * TLEN * NF + f;

    if (tid < WIN)
        swt[tid] = (0.54f - 0.46f * cospif(2.0f * (float)tid / 25.0f)) * (1.0f / 13.5f);

    // ================= forward FFT =================
    float2 a[16];
    #pragma unroll
    for (int p = 0; p < 16; p++)
        a[p] = *(const float2*)(xin + (size_t)(tid + 256 * p) * NF);
    dft16<true>(a);
    fft_twstore<true, 1>(buf, s0base, tid, a);
    __syncthreads();
    fft_load(buf, pbase, a);
    __syncthreads();
    dft16<true>(a);
    fft_twstore<true, 17>(buf, s1base, tid & ~15, a);
    __syncthreads();
    fft_load(buf, pbase, a);    // stage 2 is per-thread in-place: no barrier needed
    dft16<true>(a);
    #pragma unroll
    for (int q = 0; q < 16; q++) buf[pbase + 272 * q] = a[PI(q)];
    __syncthreads();

    // ---- top-k: series A (z from regs), then series B (z from smem)
    // split key (mag bits, enc = 4095-m): order == lax.top_k (ties -> lower m)
    {
        u32 mg[8], en[8];
        #pragma unroll
        for (int k = 0; k < 8; k++) {
            int m = tid + k * THR;
            float2 z  = a[PI(k)];
            float2 zm = buf[PAD((NFFT - m) & (NFFT - 1))];
            float ar = z.x + zm.x, ai = z.y - zm.y;     // 2*A[m]
            float mag = fmaf(ar, ar, ai * ai);
            mg[k] = __float_as_uint(mag);
            en[k] = (u32)(4095 - m);
        }
        sort8(mg, en);
        warp_topk(mg, en, warpTopM[0][wid], warpTopE[0][wid]);
        #pragma unroll
        for (int k = 0; k < 8; k++) {
            int m = tid + k * THR;
            float2 z  = buf[pbase + 272 * k];
            float2 zm = buf[PAD((NFFT - m) & (NFFT - 1))];
            float br = z.y + zm.y, bi = zm.x - z.x;      // 2*B[m]
            float mag = fmaf(br, br, bi * bi);
            mg[k] = __float_as_uint(mag);
            en[k] = (u32)(4095 - m);
        }
        sort8(mg, en);
        warp_topk(mg, en, warpTopM[1][wid], warpTopE[1][wid]);
    }
    __syncthreads();

    // ---- CTA merge: warp 0 -> series A, warp 1 -> series B; lane 8 = bin-2048 singleton
    if (wid < 2) {
        const int s = wid;
        u32 cm = 0, ce = 0;
        int p = 1;
        if (lane < 8) { cm = warpTopM[s][lane][0]; ce = warpTopE[s][lane][0]; }
        else if (lane == 8) {
            float2 z = buf[PAD(2048)];
            float mag = (s == 0) ? 4.f * z.x * z.x : 4.f * z.y * z.y;
            cm = __float_as_uint(mag); ce = (u32)(4095 - 2048);
        }
        #pragma unroll 1
        for (int it = 0; it < KTOP; it++) {
            u32 wm = __reduce_max_sync(0xffffffffu, cm);
            u32 we = __reduce_max_sync(0xffffffffu, (cm == wm) ? ce : 0u);
            if (cm == wm && ce == we) {
                int m = 4095 - (int)we;
                float2 z  = buf[PAD(m)];
                float2 zm = buf[PAD((NFFT - m) & (NFFT - 1))];
                sIdx[s][it] = m;
                sVal[s][it] = (s == 0)
                    ? make_float2(0.5f * (z.x + zm.x), 0.5f * (z.y - zm.y))
                    : make_float2(0.5f * (z.y + zm.y), 0.5f * (zm.x - z.x));
                if (lane < 8) {
                    cm = (p < KTOP) ? warpTopM[s][lane][p] : 0u;
                    ce = (p < KTOP) ? warpTopE[s][lane][p] : 0u;
                    p++;
                } else { cm = 0; ce = 0; }
            }
        }
    }
    __syncthreads();

    // zero buffer; low threads compute raw edge values from the kept bins
    #pragma unroll
    for (int u = 0; u < 16; u++)
        buf[pbase + 272 * u] = make_float2(0.f, 0.f);
    if (tid < 96) {
        int srs = tid & 1, pos = tid >> 1;
        int t = pos < 24 ? pos : TLEN - 48 + pos;
        float acc = 0.f;
        #pragma unroll
        for (int j = 0; j < KTOP; j++) {
            int m = sIdx[srs][j];
            float2 v = sVal[srs][j];
            float2 tw = g_twf[(m * t) & (NFFT - 1)];
            float coef = (m == 0 || m == 2048) ? 1.f : 2.f;
            acc = fmaf(coef * v.x, tw.x, acc);
            acc = fmaf(coef * v.y, tw.y, acc);
        }
        sraw[srs][pos] = acc * (1.0f / (float)NFFT);
    }
    __syncthreads();

    // scatter filtered bins (H carries 1/NFFT): warp 0 does series a, then b
    if (wid == 0) {
        if (lane < KTOP) {
            int m = sIdx[0][lane];
            float2 vf = cmul(sVal[0][lane], g_H[m]);
            buf[PAD(m)] = vf;
            if (m > 0 && m < 2048) buf[PAD(NFFT - m)] = make_float2(vf.x, -vf.y);
        }
        __syncwarp();
        if (lane < KTOP) {
            int m = sIdx[1][lane];
            float2 wf = cmul(sVal[1][lane], g_H[m]);
            float2 c = buf[PAD(m)];
            c.x -= wf.y; c.y += wf.x;
            buf[PAD(m)] = c;
            if (m > 0 && m < 2048) {
                float2 c2 = buf[PAD(NFFT - m)];
                c2.x += wf.y; c2.y += wf.x;
                buf[PAD(NFFT - m)] = c2;
            }
        }
    }
    __syncthreads();

    // ================= inverse FFT: stages 0,1 in smem; stage 2 -> gmem =================
    fft_load(buf, pbase, a);
    __syncthreads();
    dft16<false>(a);
    fft_twstore<false, 1>(buf, s0base, tid, a);
    __syncthreads();
    fft_load(buf, pbase, a);
    __syncthreads();
    dft16<false>(a);
    fft_twstore<false, 17>(buf, s1base, tid & ~15, a);
    __syncthreads();
    fft_load(buf, pbase, a);
    dft16<false>(a);
    #pragma unroll
    for (int q = 0; q < 16; q++) {
        int t = tid + 256 * q;
        bool interior = true;
        if (q == 0)  interior = (tid >= HALF);
        if (q == 15) interior = (tid < 256 - HALF);
        if (interior)
            *(float2*)(obase + (size_t)t * NF) = a[PI(q)];
    }

    // exact edge outputs via flip-padded direct convolution of raw values
    if (tid < 48) {
        int srs = tid & 1, j = tid >> 1;
        float acc = 0.f;
        if (j < 12) {
            #pragma unroll
            for (int n = 0; n < WIN; n++) {
                int q = j + n - HALF;
                q = q < 0 ? -1 - q : q;
                acc = fmaf(swt[n], sraw[srs][q], acc);
            }
            obase[(size_t)j * NF + srs] = acc;
        } else {
            int e = j - 12;
            #pragma unroll
            for (int n = 0; n < WIN; n++) {
                int q = e + n;
                int loc = q < 24 ? q : 47 - q;
                acc = fmaf(swt[n], sraw[srs][24 + loc], acc);
            }
            obase[(size_t)(TLEN - 12 + e) * NF + srs] = acc;
        }
    }
}

// ---------------------------------------------------------------- launch
extern "C" void kernel_launch(void* const* d_in, const int* in_sizes, int n_in,
                              void* d_out, int out_size) {
    const float* x = (const float*)d_in[0];
    float* out = (float*)d_out;

    size_t smem = BUFSZ * sizeof(float2);   // 34816 B dynamic
    init_kernel<<<16, 256>>>();
    spectral_kernel<<<NB * NF / 2, THR, smem>>>(x, out);
}